// round 15
// baseline (speedup 1.0000x reference)
#include <cuda_runtime.h>
#include <cstdint>

// Demolition_Conv2d: grouped conv (16 groups of 1->32, 3x3, pad 1) + bias,
// per-(cin,cout) 5-bit quant-dequant (scale=15/9), sum over cin.
//
// R15: R14 math (cin-pair planes, integer-bit quant accumulation) + cp.async
// double-buffered smem pipeline. Block = (b, 8-row band, cout group), 224
// threads. Per cp the tap tile is contiguous (10 padded rows x 114 f2 =
// 9120 B) -> 570 cp.async 16B copies, prefetched one cp ahead. Taps read as
// conflict-free LDS.64; LDG latency fully off the consumer path.

#define CIN   16
#define COUT  32
#define HH    112
#define WW    112
#define NB    8
#define NCP   8      // cin pairs
#define HP    114    // padded height
#define WP    114    // padded width
#define NC    4      // couts per thread
#define NS    4      // vertical pixel slots per thread
#define NTHR  224    // threads per block (112 w x 2 sub-bands)
#define TROWS 10     // staged padded rows per cp (8-row band + 2)
#define TILE16 ((TROWS * WP) / 2)   // 570 16B units per cp tile

typedef unsigned long long f2;

__device__ __align__(16) f2 g_X[NB * NCP * HP * WP];   // ~6.65 MB packed planes

__device__ __forceinline__ f2 pk2(float lo, float hi) {
    f2 r; asm("mov.b64 %0, {%1, %2};" : "=l"(r) : "f"(lo), "f"(hi)); return r;
}
__device__ __forceinline__ void fma2i(f2& acc, f2 a, f2 b) {
    asm("fma.rn.f32x2 %0, %1, %2, %0;" : "+l"(acc) : "l"(a), "l"(b));
}
__device__ __forceinline__ void add2i(f2& acc, f2 b) {
    asm("add.rn.f32x2 %0, %0, %1;" : "+l"(acc) : "l"(b));
}
__device__ __forceinline__ void addbits(unsigned& aLo, unsigned& aHi, f2 t) {
    unsigned lo, hi;
    asm("mov.b64 {%0, %1}, %2;" : "=r"(lo), "=r"(hi) : "l"(t));
    aLo += lo;
    aHi += hi;
}
__device__ __forceinline__ uint32_t smem_u32(const void* p) {
    uint32_t a;
    asm("{ .reg .u64 t; cvta.to.shared.u64 t, %1; cvt.u32.u64 %0, t; }"
        : "=r"(a) : "l"(p));
    return a;
}
__device__ __forceinline__ void cpasync16(uint32_t saddr, const void* gaddr) {
    asm volatile("cp.async.cg.shared.global [%0], [%1], 16;"
                 :: "r"(saddr), "l"(gaddr));
}
#define CP_COMMIT() asm volatile("cp.async.commit_group;" ::: "memory")
#define CP_WAIT1()  asm volatile("cp.async.wait_group 1;"  ::: "memory")
#define CP_WAIT0()  asm volatile("cp.async.wait_group 0;"  ::: "memory")

// ---------------- prepass: padded cin-pair planes (2 pairs/thread) --------
#define PPW 57   // wp pairs per row
__global__ __launch_bounds__(256)
void prepass_kernel(const float* __restrict__ x)
{
    int gid = blockIdx.x * 256 + threadIdx.x;    // [0, NB*NCP*HP*PPW)
    if (gid >= NB * NCP * HP * PPW) return;
    int pp = gid % PPW;
    int t  = gid / PPW;
    int hp = t % HP;
    int t2 = t / HP;
    int cp = t2 % NCP;
    int b  = t2 / NCP;

    int h = hp - 1;
    bool rv = (h >= 0) && (h < HH);
    const float* p0 = x + (((b * CIN + 2 * cp)     * HH + h) * WW);
    const float* p1 = x + (((b * CIN + 2 * cp + 1) * HH + h) * WW);

    ulonglong2 outv;
    int w0 = 2 * pp - 1;
    int w1 = 2 * pp;
    bool v0 = rv && (w0 >= 0) && (w0 < WW);
    bool v1 = rv && (w1 >= 0) && (w1 < WW);
    outv.x = v0 ? pk2(p0[w0], p1[w0]) : 0ULL;
    outv.y = v1 ? pk2(p0[w1], p1[w1]) : 0ULL;

    ulonglong2* dst = reinterpret_cast<ulonglong2*>(
        g_X + ((long)((b * NCP + cp) * HP + hp)) * WP) + pp;
    *dst = outv;
}

// ---------------- main kernel ----------------
// Grid: 896 blocks = 8 b x 14 bands x 8 grp (grp fastest for L2 reuse).
__global__ __launch_bounds__(NTHR)
void demolition_conv2d_kernel(const float* __restrict__ Wt,
                              const float* __restrict__ bias,
                              float* __restrict__ out)
{
    __shared__ __align__(16) f2 sE[2][TROWS * WP];   // 2 x 9120 B
    __shared__ __align__(16) f2 sW[NCP * NC * 10];   // 2560 B

    const float SCALEf = 15.0f / 9.0f;
    const float INVf   = 9.0f / 15.0f;
    const float MAGICf = 12582912.0f;        // 1.5 * 2^23
    const unsigned MAGB = 0x4B400000u;
    const unsigned BIAS16 = MAGB * 16u;      // mod 2^32

    int grp = blockIdx.x & 7;
    int pbx = blockIdx.x >> 3;               // 0..111
    int b   = pbx / 14;
    int bp  = pbx % 14;
    int h0  = bp * 8;
    int co_base = grp * NC;

    int tid = threadIdx.x;
    int w   = tid % WW;          // 0..111
    int sub = tid / WW;          // 0 or 1
    int rb  = sub * 4;           // local tap-row base

    // Stage weights (scaled, lanes = cin 2cp/2cp+1).
    for (int i = tid; i < NCP * NC * 10; i += NTHR) {
        int e  = i / 10;
        int k  = i % 10;
        int cp = e / NC;
        int lc = e % NC;
        int co = co_base + lc;
        float v0, v1;
        if (k < 9) {
            v0 = Wt[((2 * cp)     * COUT + co) * 9 + k];
            v1 = Wt[((2 * cp + 1) * COUT + co) * 9 + k];
        } else {
            v0 = bias[(2 * cp)     * COUT + co];
            v1 = bias[(2 * cp + 1) * COUT + co];
        }
        sW[i] = pk2(v0 * SCALEf, v1 * SCALEf);
    }

    const f2 MAG2 = pk2(MAGICf, MAGICf);

    // Contiguous tile source: plane(b,cp) rows h0..h0+9 (full width).
    const char* gbase = reinterpret_cast<const char*>(
        g_X + ((long)b * NCP * HP + h0) * WP);
    const long PSTRIDE_B = (long)HP * WP * 8;   // plane stride in bytes

    uint32_t s0 = smem_u32(&sE[0][0]);
    uint32_t s1 = smem_u32(&sE[1][0]);

    // Prologue: stage cp 0 and 1.
#pragma unroll
    for (int i = 0; i < 3; ++i) {
        int u = tid + i * NTHR;
        if (u < TILE16) cpasync16(s0 + u * 16, gbase + (long)u * 16);
    }
    CP_COMMIT();
#pragma unroll
    for (int i = 0; i < 3; ++i) {
        int u = tid + i * NTHR;
        if (u < TILE16) cpasync16(s1 + u * 16, gbase + PSTRIDE_B + (long)u * 16);
    }
    CP_COMMIT();

    unsigned accL[NC][NS], accH[NC][NS];
#pragma unroll
    for (int c = 0; c < NC; ++c)
#pragma unroll
        for (int s = 0; s < NS; ++s) { accL[c][s] = 0u; accH[c][s] = 0u; }

#pragma unroll 1
    for (int cp = 0; cp < NCP; ++cp) {
        if (cp + 1 < NCP) CP_WAIT1(); else CP_WAIT0();
        __syncthreads();                        // tile[cp] visible to all

        const f2* S = sE[cp & 1];

        // 6 tap rows x 3 cols from smem (conflict-free LDS.64).
        f2 tp[6][3];
#pragma unroll
        for (int r = 0; r < 6; ++r) {
#pragma unroll
            for (int k = 0; k < 3; ++k)
                tp[r][k] = S[(rb + r) * WP + w + k];
        }

        const ulonglong2* wb =
            reinterpret_cast<const ulonglong2*>(&sW[cp * NC * 10]);

#pragma unroll
        for (int c = 0; c < NC; ++c) {
            ulonglong2 w01 = wb[c * 5 + 0];
            ulonglong2 w23 = wb[c * 5 + 1];
            ulonglong2 w45 = wb[c * 5 + 2];
            ulonglong2 w67 = wb[c * 5 + 3];
            ulonglong2 w8b = wb[c * 5 + 4];   // w8, bias

#pragma unroll
            for (int s = 0; s < NS; ++s) {
                f2 y = w8b.y;
                fma2i(y, tp[s][0],     w01.x);
                fma2i(y, tp[s][1],     w01.y);
                fma2i(y, tp[s][2],     w23.x);
                fma2i(y, tp[s + 1][0], w23.y);
                fma2i(y, tp[s + 1][1], w45.x);
                fma2i(y, tp[s + 1][2], w45.y);
                fma2i(y, tp[s + 2][0], w67.x);
                fma2i(y, tp[s + 2][1], w67.y);
                fma2i(y, tp[s + 2][2], w8b.x);

                add2i(y, MAG2);                     // RNE: bits = MAGB + q
                addbits(accL[c][s], accH[c][s], y); // alu-pipe accumulation
            }
        }

        __syncthreads();                        // all done reading tile[cp]

        if (cp + 2 < NCP) {                     // stage cp+2 into freed buffer
            uint32_t sd = (cp & 1) ? s1 : s0;
            const char* gs = gbase + PSTRIDE_B * (cp + 2);
#pragma unroll
            for (int i = 0; i < 3; ++i) {
                int u = tid + i * NTHR;
                if (u < TILE16) cpasync16(sd + u * 16, gs + (long)u * 16);
            }
            CP_COMMIT();
        }
    }

    // Stores: strip 16 magic biases, convert, scale. Coalesced in w.
#pragma unroll
    for (int c = 0; c < NC; ++c) {
        int co = co_base + c;
        float* ob = out + ((long)(b * COUT + co) * HH + h0 + sub * 4) * WW + w;
#pragma unroll
        for (int s = 0; s < NS; ++s) {
            int qsum = (int)(accL[c][s] + accH[c][s] - BIAS16);
            ob[s * WW] = (float)qsum * INVf;
        }
    }
}

extern "C" void kernel_launch(void* const* d_in, const int* in_sizes, int n_in,
                              void* d_out, int out_size)
{
    const float* x    = (const float*)d_in[0];   // [8,16,112,112]
    const float* Wt   = (const float*)d_in[1];   // [16,32,1,3,3]
    const float* bias = (const float*)d_in[2];   // [16,32]
    float* out        = (float*)d_out;           // [8,32,112,112]

    // NB*NCP*HP*PPW = 415872 -> 1625 blocks of 256 (guarded).
    prepass_kernel<<<1625, 256>>>(x);
    // 896 blocks = 8 b x 14 bands x 8 cout groups.
    demolition_conv2d_kernel<<<896, NTHR>>>(Wt, bias, out);
}

// round 16
// speedup vs baseline: 1.1368x; 1.1368x over previous
#include <cuda_runtime.h>
#include <cstdint>

// Demolition_Conv2d: grouped conv (16 groups of 1->32, 3x3, pad 1) + bias,
// per-(cin,cout) 5-bit quant-dequant (scale=15/9), sum over cin.
//
// R16: R14 math + WARP-SCOPED cp.async double-buffered pipeline (no block
// barriers in the loop — R15 showed those serialize). Each warp owns a
// 16w x 8row tile; its per-cp tap tile (10 rows x 18 f2 = 1440 B) is staged
// by its own cp.async ops; ordering = per-lane wait_group + __syncwarp.

#define CIN   16
#define COUT  32
#define HH    112
#define WW    112
#define NB    8
#define NCP   8      // cin pairs
#define HP    114    // padded height
#define WP    114    // padded width
#define NC    4      // couts per thread
#define NS    4      // vertical pixel slots per thread
#define TW    18     // tap tile width (16 outputs + 2)
#define TR    10     // tap tile rows (8 outputs + 2)
#define TU    ((TR * TW * 8) / 16)   // 90 16B units per tile

typedef unsigned long long f2;

__device__ __align__(16) f2 g_X[NB * NCP * HP * WP];   // ~6.65 MB packed planes

__device__ __forceinline__ f2 pk2(float lo, float hi) {
    f2 r; asm("mov.b64 %0, {%1, %2};" : "=l"(r) : "f"(lo), "f"(hi)); return r;
}
__device__ __forceinline__ void fma2i(f2& acc, f2 a, f2 b) {
    asm("fma.rn.f32x2 %0, %1, %2, %0;" : "+l"(acc) : "l"(a), "l"(b));
}
__device__ __forceinline__ void add2i(f2& acc, f2 b) {
    asm("add.rn.f32x2 %0, %0, %1;" : "+l"(acc) : "l"(b));
}
__device__ __forceinline__ void addbits(unsigned& aLo, unsigned& aHi, f2 t) {
    unsigned lo, hi;
    asm("mov.b64 {%0, %1}, %2;" : "=r"(lo), "=r"(hi) : "l"(t));
    aLo += lo;
    aHi += hi;
}
__device__ __forceinline__ uint32_t smem_u32(const void* p) {
    uint32_t a;
    asm("{ .reg .u64 t; cvta.to.shared.u64 t, %1; cvt.u32.u64 %0, t; }"
        : "=r"(a) : "l"(p));
    return a;
}
__device__ __forceinline__ void cpasync16(uint32_t saddr, const void* gaddr) {
    asm volatile("cp.async.cg.shared.global [%0], [%1], 16;"
                 :: "r"(saddr), "l"(gaddr));
}
#define CP_COMMIT() asm volatile("cp.async.commit_group;" ::: "memory")
#define CP_WAIT1()  asm volatile("cp.async.wait_group 1;"  ::: "memory")
#define CP_WAIT0()  asm volatile("cp.async.wait_group 0;"  ::: "memory")

// ---------------- prepass: padded cin-pair planes (2 pairs/thread) --------
#define PPW 57   // wp pairs per row
__global__ __launch_bounds__(256)
void prepass_kernel(const float* __restrict__ x)
{
    int gid = blockIdx.x * 256 + threadIdx.x;    // [0, NB*NCP*HP*PPW)
    if (gid >= NB * NCP * HP * PPW) return;
    int pp = gid % PPW;
    int t  = gid / PPW;
    int hp = t % HP;
    int t2 = t / HP;
    int cp = t2 % NCP;
    int b  = t2 / NCP;

    int h = hp - 1;
    bool rv = (h >= 0) && (h < HH);
    const float* p0 = x + (((b * CIN + 2 * cp)     * HH + h) * WW);
    const float* p1 = x + (((b * CIN + 2 * cp + 1) * HH + h) * WW);

    ulonglong2 outv;
    int w0 = 2 * pp - 1;
    int w1 = 2 * pp;
    bool v0 = rv && (w0 >= 0) && (w0 < WW);
    bool v1 = rv && (w1 >= 0) && (w1 < WW);
    outv.x = v0 ? pk2(p0[w0], p1[w0]) : 0ULL;
    outv.y = v1 ? pk2(p0[w1], p1[w1]) : 0ULL;

    ulonglong2* dst = reinterpret_cast<ulonglong2*>(
        g_X + ((long)((b * NCP + cp) * HP + hp)) * WP) + pp;
    *dst = outv;
}

// ---------------- main kernel ----------------
// 6272 warps = 1568 blocks x 4. Global warp gw: grp = gw/784 (uniform per
// block: 784 = 196*4), t = gw%784: wt = t%7 (16-w tile), band = (t/7)%14
// (8-row band), b = t/98.
__global__ __launch_bounds__(128, 4)
void demolition_conv2d_kernel(const float* __restrict__ Wt,
                              const float* __restrict__ bias,
                              float* __restrict__ out)
{
    __shared__ __align__(16) f2 sT[4][2][TR * TW];   // 4 warps x 2 buf x 1440B
    __shared__ __align__(16) f2 sW[NCP * NC * 10];   // 2560 B

    const float SCALEf = 15.0f / 9.0f;
    const float INVf   = 9.0f / 15.0f;
    const float MAGICf = 12582912.0f;        // 1.5 * 2^23
    const unsigned MAGB = 0x4B400000u;
    const unsigned BIAS16 = MAGB * 16u;      // mod 2^32

    int tid  = threadIdx.x;
    int wid  = tid >> 5;
    int lane = tid & 31;
    int gw   = blockIdx.x * 4 + wid;
    int grp  = gw / 784;                 // 0..7, uniform per block
    int t    = gw % 784;
    int wt   = t % 7;
    int band = (t / 7) % 14;
    int b    = t / 98;
    int h0   = band * 8;
    int wb0  = wt * 16;
    int co_base = grp * NC;

    int wl  = lane & 15;                 // w within tile
    int sub = lane >> 4;                 // 0 or 1 (row sub-band)
    int rb  = sub * NS;                  // local tap-row base

    // Stage weights (scaled, lanes = cin 2cp/2cp+1). One block barrier total.
    for (int i = tid; i < NCP * NC * 10; i += 128) {
        int e  = i / 10;
        int k  = i % 10;
        int cp = e / NC;
        int lc = e % NC;
        int co = co_base + lc;
        float v0, v1;
        if (k < 9) {
            v0 = Wt[((2 * cp)     * COUT + co) * 9 + k];
            v1 = Wt[((2 * cp + 1) * COUT + co) * 9 + k];
        } else {
            v0 = bias[(2 * cp)     * COUT + co];
            v1 = bias[(2 * cp + 1) * COUT + co];
        }
        sW[i] = pk2(v0 * SCALEf, v1 * SCALEf);
    }
    __syncthreads();

    const f2 MAG2 = pk2(MAGICf, MAGICf);

    // Tap tile source: plane(b,cp), rows h0..h0+9, cols wb0..wb0+17.
    const char* gbase = reinterpret_cast<const char*>(
        g_X + ((long)b * NCP * HP + h0) * WP + wb0);
    const long PSTRIDE_B = (long)HP * WP * 8;

    uint32_t s0 = smem_u32(&sT[wid][0][0]);
    uint32_t s1 = smem_u32(&sT[wid][1][0]);

    // Per-lane staging map: u = lane + i*32 < 90; row = u/9, unit = u%9.
    // smem row pitch = TW*8 = 144 B; global row pitch = WP*8 = 912 B.
#define STAGE(SADDR, GSRC)                                            \
    do {                                                              \
        _Pragma("unroll")                                             \
        for (int i_ = 0; i_ < 3; ++i_) {                              \
            int u_ = lane + i_ * 32;                                  \
            if (u_ < TU) {                                            \
                int row_ = u_ / 9, un_ = u_ % 9;                      \
                cpasync16((SADDR) + row_ * 144 + un_ * 16,            \
                          (GSRC) + (long)row_ * 912 + un_ * 16);      \
            }                                                         \
        }                                                             \
        CP_COMMIT();                                                  \
    } while (0)

    STAGE(s0, gbase);                         // cp 0
    STAGE(s1, gbase + PSTRIDE_B);             // cp 1

    unsigned accL[NC][NS], accH[NC][NS];
#pragma unroll
    for (int c = 0; c < NC; ++c)
#pragma unroll
        for (int s = 0; s < NS; ++s) { accL[c][s] = 0u; accH[c][s] = 0u; }

#pragma unroll 1
    for (int cp = 0; cp < NCP; ++cp) {
        if (cp + 2 < NCP) CP_WAIT1(); else CP_WAIT0();
        __syncwarp();                         // tile[cp] visible warp-wide

        const f2* S = sT[wid][cp & 1];

        // 6 tap rows x 3 cols from smem.
        f2 tp[6][3];
#pragma unroll
        for (int r = 0; r < 6; ++r) {
#pragma unroll
            for (int k = 0; k < 3; ++k)
                tp[r][k] = S[(rb + r) * TW + wl + k];
        }

        const ulonglong2* wb =
            reinterpret_cast<const ulonglong2*>(&sW[cp * NC * 10]);

#pragma unroll
        for (int c = 0; c < NC; ++c) {
            ulonglong2 w01 = wb[c * 5 + 0];
            ulonglong2 w23 = wb[c * 5 + 1];
            ulonglong2 w45 = wb[c * 5 + 2];
            ulonglong2 w67 = wb[c * 5 + 3];
            ulonglong2 w8b = wb[c * 5 + 4];   // w8, bias

#pragma unroll
            for (int s = 0; s < NS; ++s) {
                f2 y = w8b.y;
                fma2i(y, tp[s][0],     w01.x);
                fma2i(y, tp[s][1],     w01.y);
                fma2i(y, tp[s][2],     w23.x);
                fma2i(y, tp[s + 1][0], w23.y);
                fma2i(y, tp[s + 1][1], w45.x);
                fma2i(y, tp[s + 1][2], w45.y);
                fma2i(y, tp[s + 2][0], w67.x);
                fma2i(y, tp[s + 2][1], w67.y);
                fma2i(y, tp[s + 2][2], w8b.x);

                add2i(y, MAG2);                     // RNE: bits = MAGB + q
                addbits(accL[c][s], accH[c][s], y); // alu-pipe accumulation
            }
        }

        __syncwarp();                         // all lanes done reading tile

        if (cp + 2 < NCP) {
            uint32_t sd = (cp & 1) ? s1 : s0;
            STAGE(sd, gbase + PSTRIDE_B * (cp + 2));
        }
    }

    // Stores: strip 16 magic biases, convert, scale.
#pragma unroll
    for (int c = 0; c < NC; ++c) {
        int co = co_base + c;
        float* ob = out + ((long)(b * COUT + co) * HH + h0 + sub * NS) * WW
                    + wb0 + wl;
#pragma unroll
        for (int s = 0; s < NS; ++s) {
            int qsum = (int)(accL[c][s] + accH[c][s] - BIAS16);
            ob[s * WW] = (float)qsum * INVf;
        }
    }
#undef STAGE
}

extern "C" void kernel_launch(void* const* d_in, const int* in_sizes, int n_in,
                              void* d_out, int out_size)
{
    const float* x    = (const float*)d_in[0];   // [8,16,112,112]
    const float* Wt   = (const float*)d_in[1];   // [16,32,1,3,3]
    const float* bias = (const float*)d_in[2];   // [16,32]
    float* out        = (float*)d_out;           // [8,32,112,112]

    // NB*NCP*HP*PPW = 415872 -> 1625 blocks of 256 (guarded).
    prepass_kernel<<<1625, 256>>>(x);
    // 6272 warps = 1568 blocks x 4 warps.
    demolition_conv2d_kernel<<<1568, 128>>>(Wt, bias, out);
}